// round 12
// baseline (speedup 1.0000x reference)
#include <cuda_runtime.h>
#include <math.h>
#include <float.h>

// ---------------- problem constants (fixed by setup_inputs) ----------------
#define N0_   320000
#define N1_   80000
#define N2_   16000
#define E1_   800000
#define E2_   160000
#define INC_  128
#define F1_   256      // H1*HID = 4*64
#define F2_   48       // OUT_C
#define NEG_SLOPE 0.2f

// ---------------- scratch (static device globals; no allocs) ----------------
__device__ __align__(128) float g_xl1[(size_t)N0_ * F1_];   // 327 MB
__device__ __align__(128) float g_xr1[(size_t)N1_ * F1_];   // 82 MB (also h1)
__device__ __align__(128) float g_agg1[(size_t)N1_ * F1_];  // 82 MB (xl2|xr2)
// CSR scratch
__device__ int g_cnt1[N1_], g_off1[N1_ + 1], g_cur1[N1_], g_csr1[E1_];
__device__ int g_cnt2[N2_], g_off2[N2_ + 1], g_cur2[N2_], g_csr2[E2_];

#define XL2_OFF 0
#define XR2_OFF ((size_t)N1_ * F2_)

__device__ __forceinline__ float lrelu(float v) { return v > 0.f ? v : NEG_SLOPE * v; }

// packed f32x2 helpers (Blackwell FFMA2 pipe — ptxas never auto-fuses from C++)
__device__ __forceinline__ unsigned long long pk2(float a, float b) {
    unsigned long long r;
    asm("mov.b64 %0, {%1, %2};" : "=l"(r) : "f"(a), "f"(b));
    return r;
}
__device__ __forceinline__ void fma2(unsigned long long& d, unsigned long long a,
                                     unsigned long long b) {
    asm("fma.rn.f32x2 %0, %1, %2, %3;" : "=l"(d) : "l"(a), "l"(b), "l"(d));
}
__device__ __forceinline__ float2 unpk2(unsigned long long v) {
    float2 r;
    asm("mov.b64 {%0, %1}, %2;" : "=f"(r.x), "=f"(r.y) : "l"(v));
    return r;
}

// ---------------- CSR build kernels ----------------
__global__ void zero_cnt_kernel() {
    int i = blockIdx.x * 256 + threadIdx.x;
    if (i < N1_) g_cnt1[i] = 0;
    if (i < N2_) g_cnt2[i] = 0;
}
__global__ void hist_kernel(const int* __restrict__ dst, int E, int* __restrict__ cnt) {
    int i = blockIdx.x * 256 + threadIdx.x;
    if (i < E) atomicAdd(&cnt[dst[i]], 1);
}
// single-block exclusive scan of n counts -> off[0..n], plus cursor copy
__global__ void scan_kernel(const int* __restrict__ cnt, int* __restrict__ off,
                            int* __restrict__ cur, int n) {
    __shared__ int part[1024];
    int tid = threadIdx.x;
    int chunk = (n + 1023) >> 10;
    int lo = tid * chunk;
    int hi = lo + chunk < n ? lo + chunk : n;
    int s = 0;
    for (int i = lo; i < hi; i++) s += cnt[i];
    part[tid] = s;
    __syncthreads();
    for (int d = 1; d < 1024; d <<= 1) {
        int v = (tid >= d) ? part[tid - d] : 0;
        __syncthreads();
        part[tid] += v;
        __syncthreads();
    }
    int run = part[tid] - s;   // exclusive prefix of this thread's chunk
    for (int i = lo; i < hi; i++) { off[i] = run; cur[i] = run; run += cnt[i]; }
    if (tid == 0) off[n] = part[1023];
}
__global__ void scatter_kernel(const int* __restrict__ src, const int* __restrict__ dst,
                               int E, int* __restrict__ cur, int* __restrict__ csr) {
    int i = blockIdx.x * 256 + threadIdx.x;
    if (i < E) {
        int pos = atomicAdd(&cur[dst[i]], 1);
        csr[pos] = src[i];
    }
}

// ---------------- SGEMM: C[M,N] = A[M,K] @ B[K,N] + bias ----------------
// BM=128, BN=128, BK=16, 256 threads, 8x8 micro-tile on packed f32x2 FMA.
// 2 B smem read per FFMA2 (was 3 B at 8x4) — targets the measured L1=76% bound.
// Register double-buffered k-loop.
// mode: 0 -> A=x, C=g_xl1 ; 1 -> A=x, C=g_xr1
//       2 -> A=g_xr1(h1), C=agg1[XL2] ; 3 -> A=g_xr1(h1), C=agg1[XR2]
// Requires M % 128 == 0, K % 16 == 0 (all hold). N guarded per float4.
__global__ __launch_bounds__(256)
void sgemm_bias(const float* __restrict__ Ain, const float* __restrict__ B,
                const float* __restrict__ bias, int mode, int M, int N, int K)
{
    const float* A = (mode >= 2) ? g_xr1 : Ain;
    float* C = (mode == 0) ? g_xl1 : (mode == 1) ? g_xr1
             : (mode == 2) ? (g_agg1 + XL2_OFF) : (g_agg1 + XR2_OFF);

    __shared__ float As[16][132];   // [k][m], padded
    __shared__ float Bs[16][132];   // [k][n], padded

    const int tid = threadIdx.x;
    const int tx = tid & 15;         // n micro index (8 cols: tx*8)
    const int ty = tid >> 4;         // m micro index (8 rows: ty*8)
    const int m0 = blockIdx.x * 128;
    const int n0 = blockIdx.y * 128;

    const int ar = tid >> 2;         // 0..63
    const int ak = (tid & 3) * 4;    // 0,4,8,12
    const int bk = tid >> 4;         // 0..15
    const int bn = (tid & 15) * 8;   // 0..120
    const bool bok0 = (n0 + bn + 3 < N);
    const bool bok1 = (n0 + bn + 7 < N);

    unsigned long long accp[8][4];
#pragma unroll
    for (int i = 0; i < 8; i++)
#pragma unroll
        for (int j = 0; j < 4; j++) accp[i][j] = 0ull;

    // prologue: load tile 0 into registers
    float4 a0 = *(const float4*)&A[(size_t)(m0 + ar) * K + ak];
    float4 a1 = *(const float4*)&A[(size_t)(m0 + ar + 64) * K + ak];
    float4 b0 = make_float4(0.f, 0.f, 0.f, 0.f), b1 = b0;
    if (bok0) b0 = *(const float4*)&B[(size_t)bk * N + n0 + bn];
    if (bok1) b1 = *(const float4*)&B[(size_t)bk * N + n0 + bn + 4];

    for (int k0 = 0; k0 < K; k0 += 16) {
        __syncthreads();
        As[ak + 0][ar] = a0.x; As[ak + 1][ar] = a0.y; As[ak + 2][ar] = a0.z; As[ak + 3][ar] = a0.w;
        As[ak + 0][ar + 64] = a1.x; As[ak + 1][ar + 64] = a1.y; As[ak + 2][ar + 64] = a1.z; As[ak + 3][ar + 64] = a1.w;
        *(float4*)&Bs[bk][bn] = b0;
        *(float4*)&Bs[bk][bn + 4] = b1;
        __syncthreads();

        // prefetch next tile (latency hidden behind FMA work)
        if (k0 + 16 < K) {
            a0 = *(const float4*)&A[(size_t)(m0 + ar) * K + k0 + 16 + ak];
            a1 = *(const float4*)&A[(size_t)(m0 + ar + 64) * K + k0 + 16 + ak];
            if (bok0) b0 = *(const float4*)&B[(size_t)(k0 + 16 + bk) * N + n0 + bn];
            if (bok1) b1 = *(const float4*)&B[(size_t)(k0 + 16 + bk) * N + n0 + bn + 4];
        }

#pragma unroll
        for (int kk = 0; kk < 16; ++kk) {
            float4 af0 = *(const float4*)&As[kk][ty * 8];
            float4 af1 = *(const float4*)&As[kk][ty * 8 + 4];
            const unsigned long long* bp =
                (const unsigned long long*)&Bs[kk][tx * 8];
            unsigned long long bb0 = bp[0], bb1 = bp[1], bb2 = bp[2], bb3 = bp[3];
            float am[8] = {af0.x, af0.y, af0.z, af0.w, af1.x, af1.y, af1.z, af1.w};
#pragma unroll
            for (int i = 0; i < 8; i++) {
                unsigned long long ap = pk2(am[i], am[i]);
                fma2(accp[i][0], ap, bb0);
                fma2(accp[i][1], ap, bb1);
                fma2(accp[i][2], ap, bb2);
                fma2(accp[i][3], ap, bb3);
            }
        }
    }

    const int ncol = n0 + tx * 8;
    const bool cok0 = (ncol + 3 < N);
    const bool cok1 = (ncol + 7 < N);
    float4 bbias0 = make_float4(0.f, 0.f, 0.f, 0.f), bbias1 = bbias0;
    if (cok0) bbias0 = *(const float4*)&bias[ncol];
    if (cok1) bbias1 = *(const float4*)&bias[ncol + 4];
#pragma unroll
    for (int i = 0; i < 8; i++) {
        int r = m0 + ty * 8 + i;
        if (cok0) {
            float2 p0 = unpk2(accp[i][0]);
            float2 p1 = unpk2(accp[i][1]);
            float4 o = make_float4(p0.x + bbias0.x, p0.y + bbias0.y,
                                   p1.x + bbias0.z, p1.y + bbias0.w);
            *(float4*)&C[(size_t)r * N + ncol] = o;
        }
        if (cok1) {
            float2 p2 = unpk2(accp[i][2]);
            float2 p3 = unpk2(accp[i][3]);
            float4 o = make_float4(p2.x + bbias1.x, p2.y + bbias1.y,
                                   p3.x + bbias1.z, p3.y + bbias1.w);
            *(float4*)&C[(size_t)r * N + ncol + 4] = o;
        }
    }
}

// ---------------- layer-1 fused aggregate: one warp per dst node ----------------
// Depth-2 software-pipelined gather: edges i+1 and i+2 in flight while edge i computes.
__global__ __launch_bounds__(256)
void gat1_kernel(const float* __restrict__ att, const float* __restrict__ bias1)
{
    int node = (blockIdx.x * 256 + threadIdx.x) >> 5;
    if (node >= N1_) return;
    int lane = threadIdx.x & 31;

    const float4* xr4 = (const float4*)g_xr1 + (size_t)node * 64;
    const float4* at4 = (const float4*)att;
    float4 B0 = xr4[lane], B1 = xr4[lane + 32];
    float4 C0 = at4[lane], C1 = at4[lane + 32];

    const int off = g_off1[node];
    const int deg = g_off1[node + 1] - off;

    float4 acc0 = make_float4(0.f, 0.f, 0.f, 0.f);
    float4 acc1 = make_float4(0.f, 0.f, 0.f, 0.f);
    float den0 = 0.f, den1 = 0.f;

    if (deg > 0) {
        int s0 = __ldg(&g_csr1[off]);
        const float4* x0 = (const float4*)g_xl1 + (size_t)s0 * 64;
        float4 A0 = __ldg(&x0[lane]), A1 = __ldg(&x0[lane + 32]);

        float4 Nn0, Nn1;
        if (deg > 1) {
            int s1 = __ldg(&g_csr1[off + 1]);
            const float4* x1 = (const float4*)g_xl1 + (size_t)s1 * 64;
            Nn0 = __ldg(&x1[lane]); Nn1 = __ldg(&x1[lane + 32]);
        }

        for (int i = 0; i < deg; i++) {
            float4 P0, P1;
            bool more2 = (i + 2 < deg);
            if (more2) {
                int sp = __ldg(&g_csr1[off + i + 2]);
                const float4* xp = (const float4*)g_xl1 + (size_t)sp * 64;
                P0 = __ldg(&xp[lane]); P1 = __ldg(&xp[lane + 32]);
            }

            float p0 = lrelu(A0.x + B0.x) * C0.x + lrelu(A0.y + B0.y) * C0.y
                     + lrelu(A0.z + B0.z) * C0.z + lrelu(A0.w + B0.w) * C0.w;
            float p1 = lrelu(A1.x + B1.x) * C1.x + lrelu(A1.y + B1.y) * C1.y
                     + lrelu(A1.z + B1.z) * C1.z + lrelu(A1.w + B1.w) * C1.w;
#pragma unroll
            for (int o = 8; o > 0; o >>= 1) {
                p0 += __shfl_xor_sync(0xffffffffu, p0, o);
                p1 += __shfl_xor_sync(0xffffffffu, p1, o);
            }
            float ex0 = __expf(p0), ex1 = __expf(p1);
            acc0.x += ex0 * A0.x; acc0.y += ex0 * A0.y;
            acc0.z += ex0 * A0.z; acc0.w += ex0 * A0.w;
            acc1.x += ex1 * A1.x; acc1.y += ex1 * A1.y;
            acc1.z += ex1 * A1.z; acc1.w += ex1 * A1.w;
            den0 += ex0; den1 += ex1;

            if (i + 1 < deg) { A0 = Nn0; A1 = Nn1; }
            if (more2)       { Nn0 = P0; Nn1 = P1; }
        }
    }

    float inv0 = 1.f / (den0 + 1e-16f);
    float inv1 = 1.f / (den1 + 1e-16f);
    float4 b0 = ((const float4*)bias1)[lane];
    float4 b1 = ((const float4*)bias1)[lane + 32];
    float4 o0, o1;
    o0.x = fmaxf(acc0.x * inv0 + b0.x, 0.f);
    o0.y = fmaxf(acc0.y * inv0 + b0.y, 0.f);
    o0.z = fmaxf(acc0.z * inv0 + b0.z, 0.f);
    o0.w = fmaxf(acc0.w * inv0 + b0.w, 0.f);
    o1.x = fmaxf(acc1.x * inv1 + b1.x, 0.f);
    o1.y = fmaxf(acc1.y * inv1 + b1.y, 0.f);
    o1.z = fmaxf(acc1.z * inv1 + b1.z, 0.f);
    o1.w = fmaxf(acc1.w * inv1 + b1.w, 0.f);
    float4* h = (float4*)g_xr1 + (size_t)node * 64;
    h[lane] = o0; h[lane + 32] = o1;   // safe: this warp alone touches row `node`
}

// ---------------- layer-2 fused aggregate + log_softmax: one warp per node ----------------
__global__ __launch_bounds__(256)
void gat2_kernel(const float* __restrict__ att2, const float* __restrict__ bias2,
                 float* __restrict__ out)
{
    int node = (blockIdx.x * 256 + threadIdx.x) >> 5;
    if (node >= N2_) return;
    int lane = threadIdx.x & 31;

    const float4* xl2 = (const float4*)(g_agg1 + XL2_OFF);
    const float4* xr2 = (const float4*)(g_agg1 + XR2_OFF);

    float4 B = make_float4(0.f, 0.f, 0.f, 0.f), C = B;
    if (lane < 12) {
        B = xr2[(size_t)node * 12 + lane];
        C = ((const float4*)att2)[lane];
    }

    const int off = g_off2[node], end = g_off2[node + 1];
    float4 acc = make_float4(0.f, 0.f, 0.f, 0.f);
    float den = 0.f;

    if (off < end) {
        int s = __ldg(&g_csr2[off]);
        float4 A = make_float4(0.f, 0.f, 0.f, 0.f);
        if (lane < 12) A = __ldg(&xl2[(size_t)s * 12 + lane]);

        for (int e = off; e < end; e++) {
            float4 Nv = make_float4(0.f, 0.f, 0.f, 0.f);
            bool more = (e + 1 < end);
            if (more) {
                int sn = __ldg(&g_csr2[e + 1]);
                if (lane < 12) Nv = __ldg(&xl2[(size_t)sn * 12 + lane]);
            }

            float p = lrelu(A.x + B.x) * C.x + lrelu(A.y + B.y) * C.y
                    + lrelu(A.z + B.z) * C.z + lrelu(A.w + B.w) * C.w;
#pragma unroll
            for (int o = 16; o > 0; o >>= 1) p += __shfl_xor_sync(0xffffffffu, p, o);
            float ex = __expf(p);
            acc.x += ex * A.x; acc.y += ex * A.y;
            acc.z += ex * A.z; acc.w += ex * A.w;
            den += ex;

            if (more) A = Nv;
        }
    }

    float inv = 1.f / (den + 1e-16f);
    float4 v = make_float4(0.f, 0.f, 0.f, 0.f);
    if (lane < 12) {
        float4 b = ((const float4*)bias2)[lane];
        v.x = acc.x * inv + b.x;
        v.y = acc.y * inv + b.y;
        v.z = acc.z * inv + b.z;
        v.w = acc.w * inv + b.w;
    }
    float mx = (lane < 12) ? fmaxf(fmaxf(v.x, v.y), fmaxf(v.z, v.w)) : -FLT_MAX;
#pragma unroll
    for (int o = 16; o > 0; o >>= 1) mx = fmaxf(mx, __shfl_xor_sync(0xffffffffu, mx, o));
    float se = (lane < 12)
             ? (__expf(v.x - mx) + __expf(v.y - mx) + __expf(v.z - mx) + __expf(v.w - mx)) : 0.f;
#pragma unroll
    for (int o = 16; o > 0; o >>= 1) se += __shfl_xor_sync(0xffffffffu, se, o);
    float lse = logf(se);
    if (lane < 12) {
        float4 o4 = make_float4(v.x - mx - lse, v.y - mx - lse,
                                v.z - mx - lse, v.w - mx - lse);
        ((float4*)out)[(size_t)node * 12 + lane] = o4;
    }
}

// ---------------- launch ----------------
extern "C" void kernel_launch(void* const* d_in, const int* in_sizes, int n_in,
                              void* d_out, int out_size)
{
    const float* x     = (const float*)d_in[0];
    const float* Wl1   = (const float*)d_in[1];
    const float* bl1   = (const float*)d_in[2];
    const float* Wr1   = (const float*)d_in[3];
    const float* br1   = (const float*)d_in[4];
    const float* att1  = (const float*)d_in[5];
    const float* bias1 = (const float*)d_in[6];
    const float* Wl2   = (const float*)d_in[7];
    const float* bl2   = (const float*)d_in[8];
    const float* Wr2   = (const float*)d_in[9];
    const float* br2   = (const float*)d_in[10];
    const float* att2  = (const float*)d_in[11];
    const float* bias2 = (const float*)d_in[12];
    const int* src1 = (const int*)d_in[13];
    const int* dst1 = (const int*)d_in[14];
    const int* src2 = (const int*)d_in[15];
    const int* dst2 = (const int*)d_in[16];
    float* out = (float*)d_out;

    int* cnt1; int* off1; int* cur1; int* csr1;
    int* cnt2; int* off2; int* cur2; int* csr2;
    cudaGetSymbolAddress((void**)&cnt1, g_cnt1);
    cudaGetSymbolAddress((void**)&off1, g_off1);
    cudaGetSymbolAddress((void**)&cur1, g_cur1);
    cudaGetSymbolAddress((void**)&csr1, g_csr1);
    cudaGetSymbolAddress((void**)&cnt2, g_cnt2);
    cudaGetSymbolAddress((void**)&off2, g_off2);
    cudaGetSymbolAddress((void**)&cur2, g_cur2);
    cudaGetSymbolAddress((void**)&csr2, g_csr2);

    // ---- CSR build (both layers) ----
    zero_cnt_kernel<<<(N1_ + 255) / 256, 256>>>();
    hist_kernel<<<(E1_ + 255) / 256, 256>>>(dst1, E1_, cnt1);
    hist_kernel<<<(E2_ + 255) / 256, 256>>>(dst2, E2_, cnt2);
    scan_kernel<<<1, 1024>>>(cnt1, off1, cur1, N1_);
    scan_kernel<<<1, 1024>>>(cnt2, off2, cur2, N2_);
    scatter_kernel<<<(E1_ + 255) / 256, 256>>>(src1, dst1, E1_, cur1, csr1);
    scatter_kernel<<<(E2_ + 255) / 256, 256>>>(src2, dst2, E2_, cur2, csr2);

    // ---- layer-1 transforms (BN=128 -> grid.y = 2) ----
    sgemm_bias<<<dim3(N0_ / 128, F1_ / 128), 256>>>(x, Wl1, bl1, 0, N0_, F1_, INC_);
    sgemm_bias<<<dim3(N1_ / 128, F1_ / 128), 256>>>(x, Wr1, br1, 1, N1_, F1_, INC_);

    // ---- layer-1 fused aggregation (writes h1 into g_xr1) ----
    gat1_kernel<<<(N1_ * 32 + 255) / 256, 256>>>(att1, bias1);

    // ---- layer-2 transforms (N=48 fits in one 128-wide tile) ----
    sgemm_bias<<<dim3(N1_ / 128, 1), 256>>>(x, Wl2, bl2, 2, N1_, F2_, F1_);
    sgemm_bias<<<dim3(N2_ / 128, 1), 256>>>(x, Wr2, br2, 3, N2_, F2_, F1_);

    // ---- layer-2 fused aggregation + log_softmax ----
    gat2_kernel<<<(N2_ * 32 + 255) / 256, 256>>>(att2, bias2, out);
}

// round 13
// speedup vs baseline: 2.0167x; 2.0167x over previous
#include <cuda_runtime.h>
#include <math.h>
#include <float.h>

// ---------------- problem constants (fixed by setup_inputs) ----------------
#define N0_   320000
#define N1_   80000
#define N2_   16000
#define E1_   800000
#define E2_   160000
#define INC_  128
#define F1_   256      // H1*HID = 4*64
#define F2_   48       // OUT_C
#define NEG_SLOPE 0.2f

// ---------------- scratch (static device globals; no allocs) ----------------
__device__ __align__(128) float g_xl1[(size_t)N0_ * F1_];   // 327 MB
__device__ __align__(128) float g_xr1[(size_t)N1_ * F1_];   // 82 MB (also h1)
__device__ __align__(128) float g_agg1[(size_t)N1_ * F1_];  // 82 MB (xl2|xr2)
// CSR scratch
__device__ int g_cnt1[N1_], g_off1[N1_ + 1], g_cur1[N1_], g_csr1[E1_];
__device__ int g_cnt2[N2_], g_off2[N2_ + 1], g_cur2[N2_], g_csr2[E2_];
__device__ int g_bsum[128], g_total[1];

#define XL2_OFF 0
#define XR2_OFF ((size_t)N1_ * F2_)

__device__ __forceinline__ float lrelu(float v) { return v > 0.f ? v : NEG_SLOPE * v; }

// packed f32x2 helpers (Blackwell FFMA2 pipe — ptxas never auto-fuses from C++)
__device__ __forceinline__ unsigned long long pk2(float a, float b) {
    unsigned long long r;
    asm("mov.b64 %0, {%1, %2};" : "=l"(r) : "f"(a), "f"(b));
    return r;
}
__device__ __forceinline__ void fma2(unsigned long long& d, unsigned long long a,
                                     unsigned long long b) {
    asm("fma.rn.f32x2 %0, %1, %2, %3;" : "=l"(d) : "l"(a), "l"(b), "l"(d));
}
__device__ __forceinline__ float2 unpk2(unsigned long long v) {
    float2 r;
    asm("mov.b64 {%0, %1}, %2;" : "=f"(r.x), "=f"(r.y) : "l"(v));
    return r;
}

// ---------------- CSR build kernels ----------------
__global__ void zero_cnt_kernel() {
    int i = blockIdx.x * 256 + threadIdx.x;
    if (i < N1_) g_cnt1[i] = 0;
    if (i < N2_) g_cnt2[i] = 0;
}
__global__ void hist_kernel(const int* __restrict__ dst, int E, int* __restrict__ cnt) {
    int i = blockIdx.x * 256 + threadIdx.x;
    if (i < E) atomicAdd(&cnt[dst[i]], 1);
}
// phase A: per-block inclusive scan (coalesced); writes block-local exclusive + block sums
__global__ void scan_block_kernel(const int* __restrict__ cnt, int* __restrict__ off, int n) {
    __shared__ int sh[1024];
    int tid = threadIdx.x;
    int i = blockIdx.x * 1024 + tid;
    int v = (i < n) ? cnt[i] : 0;
    sh[tid] = v;
    __syncthreads();
    for (int d = 1; d < 1024; d <<= 1) {
        int t = (tid >= d) ? sh[tid - d] : 0;
        __syncthreads();
        sh[tid] += t;
        __syncthreads();
    }
    if (i < n) off[i] = sh[tid] - v;           // block-local exclusive
    if (tid == 1023) g_bsum[blockIdx.x] = sh[1023];
}
// phase B: tiny serial exclusive scan of block sums (nb <= 79)
__global__ void scan_bsum_kernel(int nb) {
    if (threadIdx.x == 0) {
        int run = 0;
        for (int b = 0; b < nb; b++) { int t = g_bsum[b]; g_bsum[b] = run; run += t; }
        g_total[0] = run;
    }
}
// phase C: add block offsets; fill cursor copy; write off[n]
__global__ void scan_add_kernel(int* __restrict__ off, int* __restrict__ cur, int n) {
    int i = blockIdx.x * 1024 + threadIdx.x;
    if (i < n) {
        int o = off[i] + g_bsum[i >> 10];
        off[i] = o;
        cur[i] = o;
    }
    if (i == 0) off[n] = g_total[0];
}
__global__ void scatter_kernel(const int* __restrict__ src, const int* __restrict__ dst,
                               int E, int* __restrict__ cur, int* __restrict__ csr) {
    int i = blockIdx.x * 256 + threadIdx.x;
    if (i < E) {
        int pos = atomicAdd(&cur[dst[i]], 1);
        csr[pos] = src[i];
    }
}

// ---------------- SGEMM: C[M,N] = A[M,K] @ B[K,N] + bias ----------------
// BM=128, BN=64, BK=16, 256 threads, 8x4 micro-tile on packed f32x2 FMA.
// (Measured config: mode-0 = 116 us, 80 regs, L1=76%.) Register double-buffered k-loop.
// mode: 0 -> A=x, C=g_xl1 ; 1 -> A=x, C=g_xr1
//       2 -> A=g_xr1(h1), C=agg1[XL2] ; 3 -> A=g_xr1(h1), C=agg1[XR2]
__global__ __launch_bounds__(256)
void sgemm_bias(const float* __restrict__ Ain, const float* __restrict__ B,
                const float* __restrict__ bias, int mode, int M, int N, int K)
{
    const float* A = (mode >= 2) ? g_xr1 : Ain;
    float* C = (mode == 0) ? g_xl1 : (mode == 1) ? g_xr1
             : (mode == 2) ? (g_agg1 + XL2_OFF) : (g_agg1 + XR2_OFF);

    __shared__ float As[16][132];
    __shared__ float Bs[16][68];

    const int tid = threadIdx.x;
    const int tx = tid & 15;
    const int ty = tid >> 4;
    const int m0 = blockIdx.x * 128;
    const int n0 = blockIdx.y * 64;

    const int ar = tid >> 2;
    const int ak = (tid & 3) * 4;
    const int bk = tid >> 4;
    const int bn = (tid & 15) * 4;
    const bool bok = (n0 + bn + 3 < N);

    unsigned long long accp[8][2];
#pragma unroll
    for (int i = 0; i < 8; i++) { accp[i][0] = 0ull; accp[i][1] = 0ull; }

    float4 a0 = *(const float4*)&A[(size_t)(m0 + ar) * K + ak];
    float4 a1 = *(const float4*)&A[(size_t)(m0 + ar + 64) * K + ak];
    float4 b  = make_float4(0.f, 0.f, 0.f, 0.f);
    if (bok) b = *(const float4*)&B[(size_t)bk * N + n0 + bn];

    for (int k0 = 0; k0 < K; k0 += 16) {
        __syncthreads();
        As[ak + 0][ar] = a0.x; As[ak + 1][ar] = a0.y; As[ak + 2][ar] = a0.z; As[ak + 3][ar] = a0.w;
        As[ak + 0][ar + 64] = a1.x; As[ak + 1][ar + 64] = a1.y; As[ak + 2][ar + 64] = a1.z; As[ak + 3][ar + 64] = a1.w;
        *(float4*)&Bs[bk][bn] = b;
        __syncthreads();

        if (k0 + 16 < K) {
            a0 = *(const float4*)&A[(size_t)(m0 + ar) * K + k0 + 16 + ak];
            a1 = *(const float4*)&A[(size_t)(m0 + ar + 64) * K + k0 + 16 + ak];
            if (bok) b = *(const float4*)&B[(size_t)(k0 + 16 + bk) * N + n0 + bn];
        }

#pragma unroll
        for (int kk = 0; kk < 16; ++kk) {
            float4 af0 = *(const float4*)&As[kk][ty * 8];
            float4 af1 = *(const float4*)&As[kk][ty * 8 + 4];
            const unsigned long long* b64 =
                (const unsigned long long*)&Bs[kk][tx * 4];
            unsigned long long b01 = b64[0], b23 = b64[1];
            float am[8] = {af0.x, af0.y, af0.z, af0.w, af1.x, af1.y, af1.z, af1.w};
#pragma unroll
            for (int i = 0; i < 8; i++) {
                unsigned long long ap = pk2(am[i], am[i]);
                fma2(accp[i][0], ap, b01);
                fma2(accp[i][1], ap, b23);
            }
        }
    }

    const int ncol = n0 + tx * 4;
    if (ncol + 3 < N) {
        float4 bb = *(const float4*)&bias[ncol];
#pragma unroll
        for (int i = 0; i < 8; i++) {
            int r = m0 + ty * 8 + i;
            float2 p0 = unpk2(accp[i][0]);
            float2 p1 = unpk2(accp[i][1]);
            float4 o = make_float4(p0.x + bb.x, p0.y + bb.y, p1.x + bb.z, p1.y + bb.w);
            *(float4*)&C[(size_t)r * N + ncol] = o;
        }
    }
}

// ---------------- layer-1 fused aggregate: one warp per dst node ----------------
// Depth-2 software-pipelined gather: edges i+1 and i+2 in flight while edge i computes.
__global__ __launch_bounds__(256)
void gat1_kernel(const float* __restrict__ att, const float* __restrict__ bias1)
{
    int node = (blockIdx.x * 256 + threadIdx.x) >> 5;
    if (node >= N1_) return;
    int lane = threadIdx.x & 31;

    const float4* xr4 = (const float4*)g_xr1 + (size_t)node * 64;
    const float4* at4 = (const float4*)att;
    float4 B0 = xr4[lane], B1 = xr4[lane + 32];
    float4 C0 = at4[lane], C1 = at4[lane + 32];

    const int off = g_off1[node];
    const int deg = g_off1[node + 1] - off;

    float4 acc0 = make_float4(0.f, 0.f, 0.f, 0.f);
    float4 acc1 = make_float4(0.f, 0.f, 0.f, 0.f);
    float den0 = 0.f, den1 = 0.f;

    if (deg > 0) {
        int s0 = __ldg(&g_csr1[off]);
        const float4* x0 = (const float4*)g_xl1 + (size_t)s0 * 64;
        float4 A0 = __ldg(&x0[lane]), A1 = __ldg(&x0[lane + 32]);

        float4 Nn0, Nn1;
        if (deg > 1) {
            int s1 = __ldg(&g_csr1[off + 1]);
            const float4* x1 = (const float4*)g_xl1 + (size_t)s1 * 64;
            Nn0 = __ldg(&x1[lane]); Nn1 = __ldg(&x1[lane + 32]);
        }

        for (int i = 0; i < deg; i++) {
            float4 P0, P1;
            bool more2 = (i + 2 < deg);
            if (more2) {
                int sp = __ldg(&g_csr1[off + i + 2]);
                const float4* xp = (const float4*)g_xl1 + (size_t)sp * 64;
                P0 = __ldg(&xp[lane]); P1 = __ldg(&xp[lane + 32]);
            }

            float p0 = lrelu(A0.x + B0.x) * C0.x + lrelu(A0.y + B0.y) * C0.y
                     + lrelu(A0.z + B0.z) * C0.z + lrelu(A0.w + B0.w) * C0.w;
            float p1 = lrelu(A1.x + B1.x) * C1.x + lrelu(A1.y + B1.y) * C1.y
                     + lrelu(A1.z + B1.z) * C1.z + lrelu(A1.w + B1.w) * C1.w;
#pragma unroll
            for (int o = 8; o > 0; o >>= 1) {
                p0 += __shfl_xor_sync(0xffffffffu, p0, o);
                p1 += __shfl_xor_sync(0xffffffffu, p1, o);
            }
            float ex0 = __expf(p0), ex1 = __expf(p1);
            acc0.x += ex0 * A0.x; acc0.y += ex0 * A0.y;
            acc0.z += ex0 * A0.z; acc0.w += ex0 * A0.w;
            acc1.x += ex1 * A1.x; acc1.y += ex1 * A1.y;
            acc1.z += ex1 * A1.z; acc1.w += ex1 * A1.w;
            den0 += ex0; den1 += ex1;

            if (i + 1 < deg) { A0 = Nn0; A1 = Nn1; }
            if (more2)       { Nn0 = P0; Nn1 = P1; }
        }
    }

    float inv0 = 1.f / (den0 + 1e-16f);
    float inv1 = 1.f / (den1 + 1e-16f);
    float4 b0 = ((const float4*)bias1)[lane];
    float4 b1 = ((const float4*)bias1)[lane + 32];
    float4 o0, o1;
    o0.x = fmaxf(acc0.x * inv0 + b0.x, 0.f);
    o0.y = fmaxf(acc0.y * inv0 + b0.y, 0.f);
    o0.z = fmaxf(acc0.z * inv0 + b0.z, 0.f);
    o0.w = fmaxf(acc0.w * inv0 + b0.w, 0.f);
    o1.x = fmaxf(acc1.x * inv1 + b1.x, 0.f);
    o1.y = fmaxf(acc1.y * inv1 + b1.y, 0.f);
    o1.z = fmaxf(acc1.z * inv1 + b1.z, 0.f);
    o1.w = fmaxf(acc1.w * inv1 + b1.w, 0.f);
    float4* h = (float4*)g_xr1 + (size_t)node * 64;
    h[lane] = o0; h[lane + 32] = o1;   // safe: this warp alone touches row `node`
}

// ---------------- layer-2 fused aggregate + log_softmax: one warp per node ----------------
__global__ __launch_bounds__(256)
void gat2_kernel(const float* __restrict__ att2, const float* __restrict__ bias2,
                 float* __restrict__ out)
{
    int node = (blockIdx.x * 256 + threadIdx.x) >> 5;
    if (node >= N2_) return;
    int lane = threadIdx.x & 31;

    const float4* xl2 = (const float4*)(g_agg1 + XL2_OFF);
    const float4* xr2 = (const float4*)(g_agg1 + XR2_OFF);

    float4 B = make_float4(0.f, 0.f, 0.f, 0.f), C = B;
    if (lane < 12) {
        B = xr2[(size_t)node * 12 + lane];
        C = ((const float4*)att2)[lane];
    }

    const int off = g_off2[node], end = g_off2[node + 1];
    float4 acc = make_float4(0.f, 0.f, 0.f, 0.f);
    float den = 0.f;

    if (off < end) {
        int s = __ldg(&g_csr2[off]);
        float4 A = make_float4(0.f, 0.f, 0.f, 0.f);
        if (lane < 12) A = __ldg(&xl2[(size_t)s * 12 + lane]);

        for (int e = off; e < end; e++) {
            float4 Nv = make_float4(0.f, 0.f, 0.f, 0.f);
            bool more = (e + 1 < end);
            if (more) {
                int sn = __ldg(&g_csr2[e + 1]);
                if (lane < 12) Nv = __ldg(&xl2[(size_t)sn * 12 + lane]);
            }

            float p = lrelu(A.x + B.x) * C.x + lrelu(A.y + B.y) * C.y
                    + lrelu(A.z + B.z) * C.z + lrelu(A.w + B.w) * C.w;
#pragma unroll
            for (int o = 16; o > 0; o >>= 1) p += __shfl_xor_sync(0xffffffffu, p, o);
            float ex = __expf(p);
            acc.x += ex * A.x; acc.y += ex * A.y;
            acc.z += ex * A.z; acc.w += ex * A.w;
            den += ex;

            if (more) A = Nv;
        }
    }

    float inv = 1.f / (den + 1e-16f);
    float4 v = make_float4(0.f, 0.f, 0.f, 0.f);
    if (lane < 12) {
        float4 b = ((const float4*)bias2)[lane];
        v.x = acc.x * inv + b.x;
        v.y = acc.y * inv + b.y;
        v.z = acc.z * inv + b.z;
        v.w = acc.w * inv + b.w;
    }
    float mx = (lane < 12) ? fmaxf(fmaxf(v.x, v.y), fmaxf(v.z, v.w)) : -FLT_MAX;
#pragma unroll
    for (int o = 16; o > 0; o >>= 1) mx = fmaxf(mx, __shfl_xor_sync(0xffffffffu, mx, o));
    float se = (lane < 12)
             ? (__expf(v.x - mx) + __expf(v.y - mx) + __expf(v.z - mx) + __expf(v.w - mx)) : 0.f;
#pragma unroll
    for (int o = 16; o > 0; o >>= 1) se += __shfl_xor_sync(0xffffffffu, se, o);
    float lse = logf(se);
    if (lane < 12) {
        float4 o4 = make_float4(v.x - mx - lse, v.y - mx - lse,
                                v.z - mx - lse, v.w - mx - lse);
        ((float4*)out)[(size_t)node * 12 + lane] = o4;
    }
}

// ---------------- launch ----------------
extern "C" void kernel_launch(void* const* d_in, const int* in_sizes, int n_in,
                              void* d_out, int out_size)
{
    const float* x     = (const float*)d_in[0];
    const float* Wl1   = (const float*)d_in[1];
    const float* bl1   = (const float*)d_in[2];
    const float* Wr1   = (const float*)d_in[3];
    const float* br1   = (const float*)d_in[4];
    const float* att1  = (const float*)d_in[5];
    const float* bias1 = (const float*)d_in[6];
    const float* Wl2   = (const float*)d_in[7];
    const float* bl2   = (const float*)d_in[8];
    const float* Wr2   = (const float*)d_in[9];
    const float* br2   = (const float*)d_in[10];
    const float* att2  = (const float*)d_in[11];
    const float* bias2 = (const float*)d_in[12];
    const int* src1 = (const int*)d_in[13];
    const int* dst1 = (const int*)d_in[14];
    const int* src2 = (const int*)d_in[15];
    const int* dst2 = (const int*)d_in[16];
    float* out = (float*)d_out;

    int* cnt1; int* off1; int* cur1; int* csr1;
    int* cnt2; int* off2; int* cur2; int* csr2;
    cudaGetSymbolAddress((void**)&cnt1, g_cnt1);
    cudaGetSymbolAddress((void**)&off1, g_off1);
    cudaGetSymbolAddress((void**)&cur1, g_cur1);
    cudaGetSymbolAddress((void**)&csr1, g_csr1);
    cudaGetSymbolAddress((void**)&cnt2, g_cnt2);
    cudaGetSymbolAddress((void**)&off2, g_off2);
    cudaGetSymbolAddress((void**)&cur2, g_cur2);
    cudaGetSymbolAddress((void**)&csr2, g_csr2);

    // ---- CSR build, layer 1 ----
    zero_cnt_kernel<<<(N1_ + 255) / 256, 256>>>();
    hist_kernel<<<(E1_ + 255) / 256, 256>>>(dst1, E1_, cnt1);
    hist_kernel<<<(E2_ + 255) / 256, 256>>>(dst2, E2_, cnt2);
    // parallel 3-phase scan, layer 1
    scan_block_kernel<<<(N1_ + 1023) / 1024, 1024>>>(cnt1, off1, N1_);
    scan_bsum_kernel<<<1, 32>>>((N1_ + 1023) / 1024);
    scan_add_kernel<<<(N1_ + 1023) / 1024, 1024>>>(off1, cur1, N1_);
    scatter_kernel<<<(E1_ + 255) / 256, 256>>>(src1, dst1, E1_, cur1, csr1);
    // parallel 3-phase scan, layer 2 (reuses g_bsum after layer-1 scan completes)
    scan_block_kernel<<<(N2_ + 1023) / 1024, 1024>>>(cnt2, off2, N2_);
    scan_bsum_kernel<<<1, 32>>>((N2_ + 1023) / 1024);
    scan_add_kernel<<<(N2_ + 1023) / 1024, 1024>>>(off2, cur2, N2_);
    scatter_kernel<<<(E2_ + 255) / 256, 256>>>(src2, dst2, E2_, cur2, csr2);

    // ---- layer-1 transforms (measured 8x4 config) ----
    sgemm_bias<<<dim3(N0_ / 128, F1_ / 64), 256>>>(x, Wl1, bl1, 0, N0_, F1_, INC_);
    sgemm_bias<<<dim3(N1_ / 128, F1_ / 64), 256>>>(x, Wr1, br1, 1, N1_, F1_, INC_);

    // ---- layer-1 fused aggregation (writes h1 into g_xr1) ----
    gat1_kernel<<<(N1_ * 32 + 255) / 256, 256>>>(att1, bias1);

    // ---- layer-2 transforms ----
    sgemm_bias<<<dim3(N1_ / 128, 1), 256>>>(x, Wl2, bl2, 2, N1_, F2_, F1_);
    sgemm_bias<<<dim3(N2_ / 128, 1), 256>>>(x, Wr2, br2, 3, N2_, F2_, F1_);

    // ---- layer-2 fused aggregation + log_softmax ----
    gat2_kernel<<<(N2_ * 32 + 255) / 256, 256>>>(att2, bias2, out);
}